// round 10
// baseline (speedup 1.0000x reference)
#include <cuda_runtime.h>
#include <cuda_fp16.h>
#include <cstdint>

// ---------------- problem constants ----------------
#define Bc 4
#define Lc 8192
#define Dc 512
#define Hc 8
#define DKc 64
#define Ec 65           // DK + PD
#define Fc 520          // H * E
#define FP 544          // padded F (multiple of 32)
#define EH 68           // padded per-head width for KH/VH (16B aligned)
#define NSPLIT 64
#define LCHUNK (Lc / NSPLIT)   // 128

#define ATT_ELEMS  ((size_t)Bc * Lc * Dc)
#define ATTN_ELEMS ((size_t)Bc * Hc * Ec * Ec)
#define BLD ((size_t)Bc * Lc * Dc)

// ---------------- scratch (device globals; no allocs allowed) ----------------
__device__ __half g_Xh[3][BLD];                     // fp16 query/key/value
__device__ __half g_Wh[3][(size_t)Dc * Dc];         // fp16 Wq/Wk/Wv
__device__ __half g_QCh[(size_t)Bc * Lc * FP];      // concat q, fp16, pad zeroed
__device__ float  g_KH[(size_t)Bc * Hc * Lc * EH];  // LN'd k, fp32 exact
__device__ float  g_VH[(size_t)Bc * Hc * Lc * EH];  // LN'd v, fp32 exact
__device__ float  g_part[(size_t)Bc * Hc * NSPLIT * Ec * Ec];
__device__ __half g_W2Th[(size_t)Bc * Dc * FP];     // folded fc weights, fp16

// ============================================================================
// helpers
// ============================================================================
__device__ __forceinline__ uint32_t smem_u32(const void* p) {
    uint32_t a;
    asm("{ .reg .u64 t; cvta.to.shared.u64 t, %1; cvt.u32.u64 %0, t; }" : "=r"(a) : "l"(p));
    return a;
}
__device__ __forceinline__ void cp16(uint32_t dst, const void* src) {
    asm volatile("cp.async.ca.shared.global [%0], [%1], 16;" :: "r"(dst), "l"(src));
}
#define CP_COMMIT() asm volatile("cp.async.commit_group;" ::: "memory")
#define CP_WAIT0()  asm volatile("cp.async.wait_group 0;" ::: "memory")
#define CP_WAIT1()  asm volatile("cp.async.wait_group 1;" ::: "memory")

__device__ __forceinline__ void mma_f16(float c[4], const uint32_t a[4], const uint32_t b[2]) {
    asm volatile(
        "mma.sync.aligned.m16n8k16.row.col.f32.f16.f16.f32 "
        "{%0,%1,%2,%3}, {%4,%5,%6,%7}, {%8,%9}, {%0,%1,%2,%3};"
        : "+f"(c[0]), "+f"(c[1]), "+f"(c[2]), "+f"(c[3])
        : "r"(a[0]), "r"(a[1]), "r"(a[2]), "r"(a[3]), "r"(b[0]), "r"(b[1]));
}

// ============================================================================
// fp16 GEMM mainloop: C[M,N] = A[M,K] @ B[N,K]^T, fp32 accum.
// 128x128 CTA tile, 256 thr (8 warps, warp tile 64x32), K-block 32,
// cp.async 3-stage, single sync per K-block. Stage = 20.5KB -> 61.4KB smem.
// ============================================================================
#define SSTRH 40                        // smem row stride in halfs (80B, conflict-free)
#define ATILEH (128 * SSTRH)            // 5120 halfs per operand per stage
#define STAGEH (2 * ATILEH)             // 10240 halfs per stage
#define NSTAGE 3
#define SMEM_MAIN (NSTAGE * STAGEH * 2) // 61440 bytes
#define SMEM_PROJ (128 * 132 * 4)       // 67584 bytes (epilogue staging)

__device__ __forceinline__ void gemm_copy_stage(
    const __half* __restrict__ A, const __half* __restrict__ Bw,
    int lda, int m0, int n0, int kb, uint32_t sbase, int r0, int c)
{
    const int s = kb % NSTAGE;
    const int k0 = kb << 5;
    uint32_t as = sbase + (uint32_t)(s * STAGEH) * 2u;
    uint32_t bs = as + (uint32_t)ATILEH * 2u;
#pragma unroll
    for (int rr = 0; rr < 2; rr++) {
        const int row = r0 + rr * 64;
        uint32_t doff = (uint32_t)(row * SSTRH + c * 8) * 2u;
        cp16(as + doff, A + (size_t)(m0 + row) * lda + k0 + c * 8);
        cp16(bs + doff, Bw + (size_t)(n0 + row) * lda + k0 + c * 8);
    }
}

__device__ __forceinline__ void gemm_mainloop(
    const __half* __restrict__ A, const __half* __restrict__ Bw,
    int lda, int NKB, int m0, int n0,
    const __half* smh, uint32_t sbase, float acc[4][4][4])
{
    const int tid = threadIdx.x;
    const int wid = tid >> 5;
    const int lane = tid & 31;
    const int g = lane >> 2;
    const int t = lane & 3;
    const int mw = (wid >> 2) * 64;
    const int nw = (wid & 3) * 32;
    const int r0 = tid >> 2;              // copy row 0..63 (+64)
    const int cc = tid & 3;               // copy chunk

    gemm_copy_stage(A, Bw, lda, m0, n0, 0, sbase, r0, cc);
    CP_COMMIT();
    gemm_copy_stage(A, Bw, lda, m0, n0, 1, sbase, r0, cc);
    CP_COMMIT();

#pragma unroll 1
    for (int kb = 0; kb < NKB; kb++) {
        if (kb + 1 < NKB) { CP_WAIT1(); } else { CP_WAIT0(); }
        __syncthreads();
        // buffer (kb+2)%3 was computed at kb-1; sync above proves it's free.
        if (kb + 2 < NKB) {
            gemm_copy_stage(A, Bw, lda, m0, n0, kb + 2, sbase, r0, cc);
            CP_COMMIT();
        }

        const __half* As = smh + (kb % NSTAGE) * STAGEH;
        const __half* Bs = As + ATILEH;
#pragma unroll
        for (int kk = 0; kk < 32; kk += 16) {
            uint32_t af[4][4];
#pragma unroll
            for (int i = 0; i < 4; i++) {
                const __half* base = As + (mw + 16 * i + g) * SSTRH + kk + 2 * t;
                af[i][0] = *(const uint32_t*)(base);
                af[i][1] = *(const uint32_t*)(base + 8 * SSTRH);
                af[i][2] = *(const uint32_t*)(base + 8);
                af[i][3] = *(const uint32_t*)(base + 8 * SSTRH + 8);
            }
            uint32_t bf[4][2];
#pragma unroll
            for (int j = 0; j < 4; j++) {
                const __half* base = Bs + (nw + 8 * j + g) * SSTRH + kk + 2 * t;
                bf[j][0] = *(const uint32_t*)(base);
                bf[j][1] = *(const uint32_t*)(base + 8);
            }
#pragma unroll
            for (int i = 0; i < 4; i++)
#pragma unroll
                for (int j = 0; j < 4; j++)
                    mma_f16(acc[i][j], af[i], bf[j]);
        }
    }
}

// ============================================================================
// Kernel X: convert inputs/weights to fp16 (vectorized)
// ============================================================================
__global__ void xcvt(const float* __restrict__ Xq, const float* __restrict__ Xk,
                     const float* __restrict__ Xv)
{
    const int op = blockIdx.y;
    const float* X = (op == 0) ? Xq : (op == 1) ? Xk : Xv;
    const size_t i4 = (size_t)blockIdx.x * 256 + threadIdx.x;
    float4 v = ((const float4*)X)[i4];
    __half2* dst = (__half2*)(g_Xh[op] + i4 * 4);
    dst[0] = __floats2half2_rn(v.x, v.y);
    dst[1] = __floats2half2_rn(v.z, v.w);
}

__global__ void wcvt(const float* __restrict__ Wq, const float* __restrict__ Wk,
                     const float* __restrict__ Wv)
{
    const int op = blockIdx.y;
    const float* W = (op == 0) ? Wq : (op == 1) ? Wk : Wv;
    const size_t i4 = (size_t)blockIdx.x * 256 + threadIdx.x;
    float4 v = ((const float4*)W)[i4];
    __half2* dst = (__half2*)(g_Wh[op] + i4 * 4);
    dst[0] = __floats2half2_rn(v.x, v.y);
    dst[1] = __floats2half2_rn(v.z, v.w);
}

// ============================================================================
// Kernel A: fused projection + LN + concat.  grid (4, 256, 3), 256 thr.
// ============================================================================
#define CSTR 132

__global__ void __launch_bounds__(256, 2)
proj_fused(const float* __restrict__ bq, const float* __restrict__ bk,
           const float* __restrict__ bv,
           const float* __restrict__ gK, const float* __restrict__ betaK,
           const float* __restrict__ gV, const float* __restrict__ betaV,
           const float* __restrict__ pos)
{
    extern __shared__ __align__(16) char smraw[];
    __half* smh = (__half*)smraw;
    float* smf = (float*)smraw;
    const uint32_t sbase = smem_u32(smraw);
    const int mode = blockIdx.z;
    const __half* A = g_Xh[mode];
    const __half* W = g_Wh[mode];
    const float* bias = (mode == 0) ? bq : (mode == 1) ? bk : bv;
    const float* gamm = (mode == 1) ? gK : gV;
    const float* beta = (mode == 1) ? betaK : betaV;

    const int m0 = blockIdx.y * 128;
    const int n0 = blockIdx.x * 128;

    float acc[4][4][4] = {};
    gemm_mainloop(A, W, Dc, Dc / 32, m0, n0, smh, sbase, acc);

    // ---- stage tile (+bias) into smem as fp32 ----
    __syncthreads();
    const int tid = threadIdx.x;
    const int wid = tid >> 5;
    const int lane = tid & 31;
    const int g = lane >> 2;
    const int t = lane & 3;
    const int mw = (wid >> 2) * 64;
    const int nw = (wid & 3) * 32;

#pragma unroll
    for (int i = 0; i < 4; i++) {
        const int r0 = mw + 16 * i + g;
#pragma unroll
        for (int j = 0; j < 4; j++) {
            const int col = nw + 8 * j + 2 * t;
            float2 bv2 = *(const float2*)(bias + n0 + col);
            smf[r0 * CSTR + col]       = acc[i][j][0] + bv2.x;
            smf[r0 * CSTR + col + 1]   = acc[i][j][1] + bv2.y;
            smf[(r0 + 8) * CSTR + col]     = acc[i][j][2] + bv2.x;
            smf[(r0 + 8) * CSTR + col + 1] = acc[i][j][3] + bv2.y;
        }
    }
    __syncthreads();

    // ---- per-row epilogue: 8 warps x 16 rows ----
    for (int rr = 0; rr < 16; rr++) {
        const int r = wid * 16 + rr;
        const int m = m0 + r;                 // = b*L + l
        const int b = m >> 13, l = m & (Lc - 1);
        const float pv = pos[m];
#pragma unroll
        for (int hh = 0; hh < 2; hh++) {
            const int h = (n0 >> 6) + hh;
            float x0 = smf[r * CSTR + 64 * hh + lane];
            float x1 = smf[r * CSTR + 64 * hh + lane + 32];
            if (mode == 0) {
                // q concat, fp16 (out_gemm reads it directly)
                __half* qrow = &g_QCh[(size_t)m * FP + h * Ec];
                if (lane == 0) qrow[0] = __float2half_rn(pv);
                qrow[1 + lane] = __float2half_rn(x0);
                qrow[1 + lane + 32] = __float2half_rn(x1);
                if (hh == 1 && n0 == 384 && lane < (FP - Fc))
                    g_QCh[(size_t)m * FP + Fc + lane] = __float2half_rn(0.0f);
            } else {
                float s = x0 + x1, sq = x0 * x0 + x1 * x1;
#pragma unroll
                for (int off = 16; off; off >>= 1) {
                    s  += __shfl_xor_sync(0xffffffffu, s,  off);
                    sq += __shfl_xor_sync(0xffffffffu, sq, off);
                }
                float mean = s * (1.0f / 64.0f);
                float var = sq * (1.0f / 64.0f) - mean * mean;
                float rstd = rsqrtf(var + 1e-5f);
                float y0 = (x0 - mean) * rstd * gamm[h * DKc + lane] + beta[h * DKc + lane];
                float y1 = (x1 - mean) * rstd * gamm[h * DKc + lane + 32] + beta[h * DKc + lane + 32];
                float* orow = ((mode == 1) ? g_KH : g_VH) +
                              (((size_t)b * Hc + h) * Lc + l) * EH;
                if (lane == 0) orow[0] = pv;
                orow[1 + lane] = y0;
                orow[1 + lane + 32] = y1;
                if (lane < 2) orow[66 + lane] = 0.0f;   // pad cols
            }
        }
    }
}

// ============================================================================
// Kernel B: attn partials  part[b,h,s] = K_chunk^T @ V_chunk  (fp32 exact)
// grid (NSPLIT, H, B). Single sync per iteration.
// ============================================================================
__global__ void __launch_bounds__(256)
attn_partial()
{
    __shared__ __align__(16) float ks[2][16][80];
    __shared__ __align__(16) float vs[2][16][80];
    const int split = blockIdx.x, h = blockIdx.y, b = blockIdx.z;
    const int tid = threadIdx.x;
    const int td = tid >> 4;
    const int te = tid & 15;

    for (int i = tid; i < 2 * 16 * 80; i += 256) {
        ((float*)ks)[i] = 0.0f;
        ((float*)vs)[i] = 0.0f;
    }
    __syncthreads();

    const float* Kbase = g_KH + (((size_t)b * Hc + h) * Lc + (size_t)split * LCHUNK) * EH;
    const float* Vbase = g_VH + (((size_t)b * Hc + h) * Lc + (size_t)split * LCHUNK) * EH;

    auto issue = [&](int it) {
        const int buf = it & 1;
        const int l0 = it * 16;
#pragma unroll
        for (int c = 0; c < 3; c++) {
            int idx = tid + c * 256;
            if (idx < 544) {
                int arr = idx >= 272;
                int i2 = arr ? idx - 272 : idx;
                int row = i2 / 17, c4 = i2 % 17;
                const float* src = (arr ? Vbase : Kbase) + (size_t)(l0 + row) * EH + 4 * c4;
                uint32_t dst = smem_u32(arr ? &vs[buf][row][4 * c4] : &ks[buf][row][4 * c4]);
                cp16(dst, src);
            }
        }
        CP_COMMIT();
    };

    issue(0);

    float acc[5][5] = {};
#pragma unroll 1
    for (int it = 0; it < LCHUNK / 16; it++) {
        CP_WAIT0();
        __syncthreads();            // all warps done with iter it-1 -> buf (it+1)&1 free
        if (it + 1 < LCHUNK / 16) issue(it + 1);
        const int buf = it & 1;
#pragma unroll
        for (int r = 0; r < 16; r++) {
            float kv[5], vv[5];
#pragma unroll
            for (int i = 0; i < 5; i++) kv[i] = ks[buf][r][td + 16 * i];
#pragma unroll
            for (int j = 0; j < 5; j++) vv[j] = vs[buf][r][te + 16 * j];
#pragma unroll
            for (int i = 0; i < 5; i++)
#pragma unroll
                for (int j = 0; j < 5; j++)
                    acc[i][j] += kv[i] * vv[j];
        }
    }

    float* out = &g_part[(((size_t)b * Hc + h) * NSPLIT + split) * Ec * Ec];
#pragma unroll
    for (int i = 0; i < 5; i++) {
        int d = td + 16 * i;
        if (d >= Ec) continue;
#pragma unroll
        for (int j = 0; j < 5; j++) {
            int e = te + 16 * j;
            if (e < Ec) out[d * Ec + e] = acc[i][j];
        }
    }
}

// ============================================================================
// Kernel C: reduce partials, scale by 1/L
// ============================================================================
__global__ void attn_reduce(float* __restrict__ attn_out)
{
    const size_t idx = (size_t)blockIdx.x * blockDim.x + threadIdx.x;
    if (idx >= ATTN_ELEMS) return;
    const size_t bh = idx / (Ec * Ec);
    const size_t de = idx % (Ec * Ec);
    float s = 0.0f;
#pragma unroll
    for (int sp = 0; sp < NSPLIT; sp++)
        s += g_part[(bh * NSPLIT + sp) * (Ec * Ec) + de];
    attn_out[idx] = s * (1.0f / (float)Lc);
}

// ============================================================================
// Kernel D: W2Th[b,o,h*65+d] = sum_e attn[b,h,d,e]*fcW[o,h*65+e]   (fp16 out)
// Each thread computes 4 consecutive d for one o: LDS.128 on sa per e.
// ============================================================================
__global__ void __launch_bounds__(256)
w2t_kernel(const float* __restrict__ attn, const float* __restrict__ fcW)
{
    const int og = blockIdx.x;          // 0..7 (64 o's each)
    const int bh = blockIdx.y;          // 0..31
    const int b = bh >> 3, h = bh & 7;
    __shared__ __align__(16) float sa[Ec * 68];   // sa[e*68 + d] = attn[d][e]
    __shared__ float sw[64 * 66];                 // sw[o*66 + e]
    const int tid = threadIdx.x;

    for (int i = tid; i < Ec * 68; i += 256) sa[i] = 0.0f;
    __syncthreads();
    for (int i = tid; i < Ec * Ec; i += 256) {
        int d = i / Ec, e = i % Ec;
        sa[e * 68 + d] = attn[((size_t)bh * Ec + d) * Ec + e];
    }
    for (int i = tid; i < 64 * Ec; i += 256) {
        int o = i / Ec, e = i % Ec;
        sw[o * 66 + e] = fcW[(size_t)(og * 64 + o) * Fc + h * Ec + e];
    }
    __syncthreads();

    // 64 o x 17 d-groups (of 4) = 1088 work items
    for (int idx = tid; idx < 64 * 17; idx += 256) {
        const int o = idx / 17;
        const int d0 = (idx % 17) * 4;
        const float* wr = &sw[o * 66];
        float s0 = 0, s1 = 0, s2 = 0, s3 = 0;
#pragma unroll
        for (int e = 0; e < Ec; e++) {
            float4 a4 = *(const float4*)&sa[e * 68 + d0];
            float w = wr[e];
            s0 += w * a4.x; s1 += w * a4.y; s2 += w * a4.z; s3 += w * a4.w;
        }
        __half* dst = &g_W2Th[((size_t)b * Dc + og * 64 + o) * FP + h * Ec + d0];
        dst[0] = __float2half_rn(s0);
        if (d0 + 1 < Ec) dst[1] = __float2half_rn(s1);
        if (d0 + 2 < Ec) dst[2] = __float2half_rn(s2);
        if (d0 + 3 < Ec) dst[3] = __float2half_rn(s3);
    }
    if (h == 0) {
        for (int i = tid; i < 64 * (FP - Fc); i += 256) {
            int o = og * 64 + i / (FP - Fc), cc = Fc + i % (FP - Fc);
            g_W2Th[((size_t)b * Dc + o) * FP + cc] = __float2half_rn(0.0f);
        }
    }
}

// ============================================================================
// Kernel E: out[b] = QCh[b] @ W2Th[b]^T + fcb.  grid (4, 64, 4), 256 thr.
// ============================================================================
__global__ void __launch_bounds__(256, 2)
out_gemm(const float* __restrict__ fcb, float* __restrict__ out)
{
    extern __shared__ __align__(16) char smraw[];
    __half* smh = (__half*)smraw;
    const uint32_t sbase = smem_u32(smraw);
    const int b = blockIdx.z;
    const __half* A  = g_QCh + (size_t)b * Lc * FP;
    const __half* Bw = g_W2Th + (size_t)b * Dc * FP;
    float* C = out + (size_t)b * Lc * Dc;

    const int m0 = blockIdx.y * 128;
    const int n0 = blockIdx.x * 128;

    float acc[4][4][4] = {};
    gemm_mainloop(A, Bw, FP, FP / 32, m0, n0, smh, sbase, acc);

    const int tid = threadIdx.x;
    const int wid = tid >> 5;
    const int lane = tid & 31;
    const int g = lane >> 2;
    const int t = lane & 3;
    const int mw = (wid >> 2) * 64;
    const int nw = (wid & 3) * 32;

#pragma unroll
    for (int i = 0; i < 4; i++) {
        const int row0 = m0 + mw + 16 * i + g;
#pragma unroll
        for (int j = 0; j < 4; j++) {
            const int col = n0 + nw + 8 * j + 2 * t;
            float2 bv = *(const float2*)(fcb + col);
            float2 o0, o1;
            o0.x = acc[i][j][0] + bv.x;  o0.y = acc[i][j][1] + bv.y;
            o1.x = acc[i][j][2] + bv.x;  o1.y = acc[i][j][3] + bv.y;
            *(float2*)(C + (size_t)row0 * Dc + col) = o0;
            *(float2*)(C + (size_t)(row0 + 8) * Dc + col) = o1;
        }
    }
}

// ============================================================================
// launch
// ============================================================================
extern "C" void kernel_launch(void* const* d_in, const int* in_sizes, int n_in,
                              void* d_out, int out_size)
{
    const float* query = (const float*)d_in[0];
    const float* key   = (const float*)d_in[1];
    const float* value = (const float*)d_in[2];
    const float* pos   = (const float*)d_in[3];
    const float* Wq    = (const float*)d_in[4];
    const float* bq    = (const float*)d_in[5];
    const float* Wk    = (const float*)d_in[6];
    const float* bk    = (const float*)d_in[7];
    const float* Wv    = (const float*)d_in[8];
    const float* bv    = (const float*)d_in[9];
    const float* gK    = (const float*)d_in[10];
    const float* betaK = (const float*)d_in[11];
    const float* gV    = (const float*)d_in[12];
    const float* betaV = (const float*)d_in[13];
    const float* fcW   = (const float*)d_in[14];
    const float* fcb   = (const float*)d_in[15];

    float* att_out  = (float*)d_out;
    float* attn_out = att_out + ATT_ELEMS;

    cudaFuncSetAttribute(proj_fused, cudaFuncAttributeMaxDynamicSharedMemorySize, SMEM_PROJ);
    cudaFuncSetAttribute(out_gemm,  cudaFuncAttributeMaxDynamicSharedMemorySize, SMEM_MAIN);

    // 0) convert inputs + weights to fp16
    xcvt<<<dim3((unsigned)(BLD / 4 / 256), 3), 256>>>(query, key, value);
    wcvt<<<dim3(Dc * Dc / 4 / 256, 3), 256>>>(Wq, Wk, Wv);
    // 1) fused projections + LN + concat (fp16 MMA, fp32 accum)
    proj_fused<<<dim3(4, 256, 3), 256, SMEM_PROJ>>>(bq, bk, bv,
                                                     gK, betaK, gV, betaV, pos);
    // 2) attn partials (deterministic split over L, fp32 exact)
    attn_partial<<<dim3(NSPLIT, Hc, Bc), 256>>>();
    // 3) reduce + scale -> attn output
    attn_reduce<<<(unsigned)((ATTN_ELEMS + 255) / 256), 256>>>(attn_out);
    // 4) fold attn into fc weights (fp16 out)
    w2t_kernel<<<dim3(8, Bc * Hc), 256>>>(attn_out, fcW);
    // 5) output GEMM (fp16 MMA), batched over z
    out_gemm<<<dim3(4, 64, Bc), 256, SMEM_MAIN>>>(fcb, att_out);
}

// round 11
// speedup vs baseline: 1.7242x; 1.7242x over previous
#include <cuda_runtime.h>
#include <cuda_fp16.h>
#include <cstdint>

// ---------------- problem constants ----------------
#define Bc 4
#define Lc 8192
#define Dc 512
#define Hc 8
#define DKc 64
#define Ec 65           // DK + PD
#define Fc 520          // H * E
#define FP 544          // padded F (multiple of 32)
#define EH 68           // padded per-head width for KH/VH (16B aligned)
#define NSPLIT 16
#define LCHUNK (Lc / NSPLIT)   // 512

#define ATT_ELEMS  ((size_t)Bc * Lc * Dc)
#define ATTN_ELEMS ((size_t)Bc * Hc * Ec * Ec)
#define BLD ((size_t)Bc * Lc * Dc)

// ---------------- scratch (device globals; no allocs allowed) ----------------
__device__ __half g_Xh[3][BLD];                     // fp16 query/key/value
__device__ __half g_Wh[3][(size_t)Dc * Dc];         // fp16 Wq/Wk/Wv
__device__ __half g_QCh[(size_t)Bc * Lc * FP];      // concat q, fp16, pad zeroed
__device__ float  g_KH[(size_t)Bc * Hc * Lc * EH];  // LN'd k, fp32 exact
__device__ float  g_VH[(size_t)Bc * Hc * Lc * EH];  // LN'd v, fp32 exact
__device__ float  g_part[(size_t)Bc * Hc * NSPLIT * Ec * Ec];
__device__ __half g_W2Th[(size_t)Bc * Dc * FP];     // folded fc weights, fp16

// ============================================================================
// helpers
// ============================================================================
__device__ __forceinline__ uint32_t smem_u32(const void* p) {
    uint32_t a;
    asm("{ .reg .u64 t; cvta.to.shared.u64 t, %1; cvt.u32.u64 %0, t; }" : "=r"(a) : "l"(p));
    return a;
}
__device__ __forceinline__ void cp16(uint32_t dst, const void* src) {
    asm volatile("cp.async.ca.shared.global [%0], [%1], 16;" :: "r"(dst), "l"(src));
}
#define CP_COMMIT() asm volatile("cp.async.commit_group;" ::: "memory")
#define CP_WAIT0()  asm volatile("cp.async.wait_group 0;" ::: "memory")
#define CP_WAIT1()  asm volatile("cp.async.wait_group 1;" ::: "memory")

__device__ __forceinline__ void mma_f16(float c[4], const uint32_t a[4], const uint32_t b[2]) {
    asm volatile(
        "mma.sync.aligned.m16n8k16.row.col.f32.f16.f16.f32 "
        "{%0,%1,%2,%3}, {%4,%5,%6,%7}, {%8,%9}, {%0,%1,%2,%3};"
        : "+f"(c[0]), "+f"(c[1]), "+f"(c[2]), "+f"(c[3])
        : "r"(a[0]), "r"(a[1]), "r"(a[2]), "r"(a[3]), "r"(b[0]), "r"(b[1]));
}
__device__ __forceinline__ uint32_t packh2(float a, float b) {
    __half2 h = __floats2half2_rn(a, b);
    return *(uint32_t*)&h;
}

// ============================================================================
// fp16 GEMM mainloop: C[M,N] = A[M,K] @ B[N,K]^T, fp32 accum.
// 128x128 CTA tile, 256 thr (8 warps, warp tile 64x32), K-block 32,
// cp.async 3-stage, single sync per K-block.
// ============================================================================
#define SSTRH 40                        // smem row stride in halfs (80B, conflict-free)
#define ATILEH (128 * SSTRH)            // 5120 halfs per operand per stage
#define STAGEH (2 * ATILEH)             // 10240 halfs per stage
#define NSTAGE 3
#define SMEM_MAIN (NSTAGE * STAGEH * 2) // 61440 bytes
#define SMEM_PROJ (128 * 132 * 4)       // 67584 bytes (epilogue staging)

__device__ __forceinline__ void gemm_copy_stage(
    const __half* __restrict__ A, const __half* __restrict__ Bw,
    int lda, int m0, int n0, int kb, uint32_t sbase, int r0, int c)
{
    const int s = kb % NSTAGE;
    const int k0 = kb << 5;
    uint32_t as = sbase + (uint32_t)(s * STAGEH) * 2u;
    uint32_t bs = as + (uint32_t)ATILEH * 2u;
#pragma unroll
    for (int rr = 0; rr < 2; rr++) {
        const int row = r0 + rr * 64;
        uint32_t doff = (uint32_t)(row * SSTRH + c * 8) * 2u;
        cp16(as + doff, A + (size_t)(m0 + row) * lda + k0 + c * 8);
        cp16(bs + doff, Bw + (size_t)(n0 + row) * lda + k0 + c * 8);
    }
}

__device__ __forceinline__ void gemm_mainloop(
    const __half* __restrict__ A, const __half* __restrict__ Bw,
    int lda, int NKB, int m0, int n0,
    const __half* smh, uint32_t sbase, float acc[4][4][4])
{
    const int tid = threadIdx.x;
    const int wid = tid >> 5;
    const int lane = tid & 31;
    const int g = lane >> 2;
    const int t = lane & 3;
    const int mw = (wid >> 2) * 64;
    const int nw = (wid & 3) * 32;
    const int r0 = tid >> 2;              // copy row 0..63 (+64)
    const int cc = tid & 3;               // copy chunk

    gemm_copy_stage(A, Bw, lda, m0, n0, 0, sbase, r0, cc);
    CP_COMMIT();
    gemm_copy_stage(A, Bw, lda, m0, n0, 1, sbase, r0, cc);
    CP_COMMIT();

#pragma unroll 1
    for (int kb = 0; kb < NKB; kb++) {
        if (kb + 1 < NKB) { CP_WAIT1(); } else { CP_WAIT0(); }
        __syncthreads();
        if (kb + 2 < NKB) {
            gemm_copy_stage(A, Bw, lda, m0, n0, kb + 2, sbase, r0, cc);
            CP_COMMIT();
        }

        const __half* As = smh + (kb % NSTAGE) * STAGEH;
        const __half* Bs = As + ATILEH;
#pragma unroll
        for (int kk = 0; kk < 32; kk += 16) {
            uint32_t af[4][4];
#pragma unroll
            for (int i = 0; i < 4; i++) {
                const __half* base = As + (mw + 16 * i + g) * SSTRH + kk + 2 * t;
                af[i][0] = *(const uint32_t*)(base);
                af[i][1] = *(const uint32_t*)(base + 8 * SSTRH);
                af[i][2] = *(const uint32_t*)(base + 8);
                af[i][3] = *(const uint32_t*)(base + 8 * SSTRH + 8);
            }
            uint32_t bf[4][2];
#pragma unroll
            for (int j = 0; j < 4; j++) {
                const __half* base = Bs + (nw + 8 * j + g) * SSTRH + kk + 2 * t;
                bf[j][0] = *(const uint32_t*)(base);
                bf[j][1] = *(const uint32_t*)(base + 8);
            }
#pragma unroll
            for (int i = 0; i < 4; i++)
#pragma unroll
                for (int j = 0; j < 4; j++)
                    mma_f16(acc[i][j], af[i], bf[j]);
        }
    }
}

// ============================================================================
// Kernel X: convert inputs/weights to fp16 (vectorized)
// ============================================================================
__global__ void xcvt(const float* __restrict__ Xq, const float* __restrict__ Xk,
                     const float* __restrict__ Xv)
{
    const int op = blockIdx.y;
    const float* X = (op == 0) ? Xq : (op == 1) ? Xk : Xv;
    const size_t i4 = (size_t)blockIdx.x * 256 + threadIdx.x;
    float4 v = ((const float4*)X)[i4];
    __half2* dst = (__half2*)(g_Xh[op] + i4 * 4);
    dst[0] = __floats2half2_rn(v.x, v.y);
    dst[1] = __floats2half2_rn(v.z, v.w);
}

__global__ void wcvt(const float* __restrict__ Wq, const float* __restrict__ Wk,
                     const float* __restrict__ Wv)
{
    const int op = blockIdx.y;
    const float* W = (op == 0) ? Wq : (op == 1) ? Wk : Wv;
    const size_t i4 = (size_t)blockIdx.x * 256 + threadIdx.x;
    float4 v = ((const float4*)W)[i4];
    __half2* dst = (__half2*)(g_Wh[op] + i4 * 4);
    dst[0] = __floats2half2_rn(v.x, v.y);
    dst[1] = __floats2half2_rn(v.z, v.w);
}

// ============================================================================
// Kernel A: fused projection + LN + concat.  grid (4, 256, 3), 256 thr.
// ============================================================================
#define CSTR 132

__global__ void __launch_bounds__(256, 2)
proj_fused(const float* __restrict__ bq, const float* __restrict__ bk,
           const float* __restrict__ bv,
           const float* __restrict__ gK, const float* __restrict__ betaK,
           const float* __restrict__ gV, const float* __restrict__ betaV,
           const float* __restrict__ pos)
{
    extern __shared__ __align__(16) char smraw[];
    __half* smh = (__half*)smraw;
    float* smf = (float*)smraw;
    const uint32_t sbase = smem_u32(smraw);
    const int mode = blockIdx.z;
    const __half* A = g_Xh[mode];
    const __half* W = g_Wh[mode];
    const float* bias = (mode == 0) ? bq : (mode == 1) ? bk : bv;
    const float* gamm = (mode == 1) ? gK : gV;
    const float* beta = (mode == 1) ? betaK : betaV;

    const int m0 = blockIdx.y * 128;
    const int n0 = blockIdx.x * 128;

    float acc[4][4][4] = {};
    gemm_mainloop(A, W, Dc, Dc / 32, m0, n0, smh, sbase, acc);

    // ---- stage tile (+bias) into smem as fp32 ----
    __syncthreads();
    const int tid = threadIdx.x;
    const int wid = tid >> 5;
    const int lane = tid & 31;
    const int g = lane >> 2;
    const int t = lane & 3;
    const int mw = (wid >> 2) * 64;
    const int nw = (wid & 3) * 32;

#pragma unroll
    for (int i = 0; i < 4; i++) {
        const int r0 = mw + 16 * i + g;
#pragma unroll
        for (int j = 0; j < 4; j++) {
            const int col = nw + 8 * j + 2 * t;
            float2 bv2 = *(const float2*)(bias + n0 + col);
            smf[r0 * CSTR + col]       = acc[i][j][0] + bv2.x;
            smf[r0 * CSTR + col + 1]   = acc[i][j][1] + bv2.y;
            smf[(r0 + 8) * CSTR + col]     = acc[i][j][2] + bv2.x;
            smf[(r0 + 8) * CSTR + col + 1] = acc[i][j][3] + bv2.y;
        }
    }
    __syncthreads();

    // ---- per-row epilogue: 8 warps x 16 rows ----
    for (int rr = 0; rr < 16; rr++) {
        const int r = wid * 16 + rr;
        const int m = m0 + r;                 // = b*L + l
        const int b = m >> 13, l = m & (Lc - 1);
        const float pv = pos[m];
#pragma unroll
        for (int hh = 0; hh < 2; hh++) {
            const int h = (n0 >> 6) + hh;
            float x0 = smf[r * CSTR + 64 * hh + lane];
            float x1 = smf[r * CSTR + 64 * hh + lane + 32];
            if (mode == 0) {
                __half* qrow = &g_QCh[(size_t)m * FP + h * Ec];
                if (lane == 0) qrow[0] = __float2half_rn(pv);
                qrow[1 + lane] = __float2half_rn(x0);
                qrow[1 + lane + 32] = __float2half_rn(x1);
                if (hh == 1 && n0 == 384 && lane < (FP - Fc))
                    g_QCh[(size_t)m * FP + Fc + lane] = __float2half_rn(0.0f);
            } else {
                float s = x0 + x1, sq = x0 * x0 + x1 * x1;
#pragma unroll
                for (int off = 16; off; off >>= 1) {
                    s  += __shfl_xor_sync(0xffffffffu, s,  off);
                    sq += __shfl_xor_sync(0xffffffffu, sq, off);
                }
                float mean = s * (1.0f / 64.0f);
                float var = sq * (1.0f / 64.0f) - mean * mean;
                float rstd = rsqrtf(var + 1e-5f);
                float y0 = (x0 - mean) * rstd * gamm[h * DKc + lane] + beta[h * DKc + lane];
                float y1 = (x1 - mean) * rstd * gamm[h * DKc + lane + 32] + beta[h * DKc + lane + 32];
                float* orow = ((mode == 1) ? g_KH : g_VH) +
                              (((size_t)b * Hc + h) * Lc + l) * EH;
                if (lane == 0) orow[0] = pv;
                orow[1 + lane] = y0;
                orow[1 + lane + 32] = y1;
                if (lane < 3) orow[65 + lane] = 0.0f;   // pad cols 65..67
            }
        }
    }
}

// ============================================================================
// Kernel B: attn partials via fp16 MMA.
// part[b,h,s][d][e] = sum_l K[l][d] * V[l][e] over the split's L-chunk.
// Tiles M=N=96 (pad of 65), K-chunk 32. Fragments built by TRANSPOSED smem
// reads of the [l][68] fp32 tiles, packed to half2 on the fly (conflict-free:
// addr_word = 136t + g + c covers distinct banks).  fp32 accum, fixed order.
// ============================================================================
#define AST 68                          // smem row stride (floats) for K/V tiles
#define ATILE_F (32 * AST)              // 2176 floats per operand per stage
#define ASTG (2 * ATILE_F)              // 4352 floats per stage
#define ANST 3
#define SMEM_ATTN ((ANST * ASTG + 64) * 4)   // 52480 bytes (pad for OOB-safe reads)

__global__ void __launch_bounds__(256, 2)
attn_mma()
{
    extern __shared__ __align__(16) float smf[];
    const uint32_t sbase = smem_u32(smf);
    const int split = blockIdx.x, h = blockIdx.y, b = blockIdx.z;
    const int tid = threadIdx.x;
    const int wid = tid >> 5, lane = tid & 31;
    const int g = lane >> 2, t = lane & 3;
    const int mw = (wid >> 2) * 48;       // 2 warp-rows of 48
    const int nw = (wid & 3) * 24;        // 4 warp-cols of 24
    const int NKB = LCHUNK / 32;          // 16

    const float* Kb = g_KH + (((size_t)b * Hc + h) * Lc + (size_t)split * LCHUNK) * EH;
    const float* Vb = g_VH + (((size_t)b * Hc + h) * Lc + (size_t)split * LCHUNK) * EH;

    auto issue = [&](int kb) {
        const int s = kb % ANST;
        const int l0 = kb << 5;
        uint32_t base = sbase + (uint32_t)(s * ASTG) * 4u;
#pragma unroll
        for (int c = 0; c < 5; c++) {
            int idx = tid + (c << 8);
            if (idx < 1088) {
                int op = idx >= 544;
                int i2 = op ? idx - 544 : idx;
                int row = i2 / 17, ch = i2 % 17;
                const float* src = (op ? Vb : Kb) + (size_t)(l0 + row) * EH + 4 * ch;
                cp16(base + (uint32_t)(op * ATILE_F + row * AST + 4 * ch) * 4u, src);
            }
        }
        CP_COMMIT();
    };

    issue(0);
    issue(1);

    // validity predicates (d,e <= 64 are real; 65..67 are stored zeros; >=68 OOB)
    bool mok0[3], mok1[3], nok[3];
#pragma unroll
    for (int i = 0; i < 3; i++) {
        int d = mw + 16 * i + g;
        mok0[i] = (d < EH);
        mok1[i] = (d + 8 < EH);
    }
#pragma unroll
    for (int j = 0; j < 3; j++) nok[j] = (nw + 8 * j + g < EH);

    float acc[3][3][4] = {};

#pragma unroll 1
    for (int kb = 0; kb < NKB; kb++) {
        if (kb + 1 < NKB) { CP_WAIT1(); } else { CP_WAIT0(); }
        __syncthreads();
        if (kb + 2 < NKB) issue(kb + 2);

        const float* ks = smf + (kb % ANST) * ASTG;
        const float* vs = ks + ATILE_F;
#pragma unroll
        for (int kk = 0; kk < 32; kk += 16) {
            const float* k0p = ks + (kk + 2 * t) * AST;       // l = kk+2t
            const float* v0p = vs + (kk + 2 * t) * AST;
            uint32_t af[3][4];
#pragma unroll
            for (int i = 0; i < 3; i++) {
                int d = mw + 16 * i + g;
                af[i][0] = mok0[i] ? packh2(k0p[d],            k0p[AST + d])            : 0u;
                af[i][1] = mok1[i] ? packh2(k0p[d + 8],        k0p[AST + d + 8])        : 0u;
                af[i][2] = mok0[i] ? packh2(k0p[8 * AST + d],  k0p[9 * AST + d])        : 0u;
                af[i][3] = mok1[i] ? packh2(k0p[8 * AST + d + 8], k0p[9 * AST + d + 8]) : 0u;
            }
            uint32_t bf[3][2];
#pragma unroll
            for (int j = 0; j < 3; j++) {
                int e = nw + 8 * j + g;
                bf[j][0] = nok[j] ? packh2(v0p[e],           v0p[AST + e])      : 0u;
                bf[j][1] = nok[j] ? packh2(v0p[8 * AST + e], v0p[9 * AST + e])  : 0u;
            }
#pragma unroll
            for (int i = 0; i < 3; i++)
#pragma unroll
                for (int j = 0; j < 3; j++)
                    mma_f16(acc[i][j], af[i], bf[j]);
        }
    }

    // store partials (valid region 65x65 only)
    float* out = &g_part[(((size_t)b * Hc + h) * NSPLIT + split) * Ec * Ec];
#pragma unroll
    for (int i = 0; i < 3; i++) {
        const int m = mw + 16 * i + g;
#pragma unroll
        for (int j = 0; j < 3; j++) {
            const int n = nw + 8 * j + 2 * t;
            if (m < Ec) {
                if (n < Ec)     out[m * Ec + n]     = acc[i][j][0];
                if (n + 1 < Ec) out[m * Ec + n + 1] = acc[i][j][1];
            }
            if (m + 8 < Ec) {
                if (n < Ec)     out[(m + 8) * Ec + n]     = acc[i][j][2];
                if (n + 1 < Ec) out[(m + 8) * Ec + n + 1] = acc[i][j][3];
            }
        }
    }
}

// ============================================================================
// Kernel C: reduce partials, scale by 1/L
// ============================================================================
__global__ void attn_reduce(float* __restrict__ attn_out)
{
    const size_t idx = (size_t)blockIdx.x * blockDim.x + threadIdx.x;
    if (idx >= ATTN_ELEMS) return;
    const size_t bh = idx / (Ec * Ec);
    const size_t de = idx % (Ec * Ec);
    float s = 0.0f;
#pragma unroll
    for (int sp = 0; sp < NSPLIT; sp++)
        s += g_part[(bh * NSPLIT + sp) * (Ec * Ec) + de];
    attn_out[idx] = s * (1.0f / (float)Lc);
}

// ============================================================================
// Kernel D: W2Th[b,o,h*65+d] = sum_e attn[b,h,d,e]*fcW[o,h*65+e]   (fp16 out)
// ============================================================================
__global__ void __launch_bounds__(256)
w2t_kernel(const float* __restrict__ attn, const float* __restrict__ fcW)
{
    const int og = blockIdx.x;          // 0..7 (64 o's each)
    const int bh = blockIdx.y;          // 0..31
    const int b = bh >> 3, h = bh & 7;
    __shared__ float sa[Ec * 68];       // sa[e*68 + d] = attn[d][e]  (transposed)
    __shared__ float sw[64 * 66];       // sw[o*66 + e] = fcW row
    const int tid = threadIdx.x;

    for (int i = tid; i < Ec * Ec; i += 256) {
        int d = i / Ec, e = i % Ec;
        sa[e * 68 + d] = attn[((size_t)bh * Ec + d) * Ec + e];
    }
    for (int i = tid; i < 64 * Ec; i += 256) {
        int o = i / Ec, e = i % Ec;
        sw[o * 66 + e] = fcW[(size_t)(og * 64 + o) * Fc + h * Ec + e];
    }
    __syncthreads();

    for (int idx = tid; idx < 64 * Ec; idx += 256) {
        int o = idx / Ec, d = idx % Ec;   // consecutive threads -> consecutive d
        const float* wr = &sw[o * 66];
        float s = 0.0f;
#pragma unroll
        for (int e = 0; e < Ec; e++) s += wr[e] * sa[e * 68 + d];
        g_W2Th[((size_t)b * Dc + og * 64 + o) * FP + h * Ec + d] = __float2half_rn(s);
    }
    if (h == 0) {
        for (int i = tid; i < 64 * (FP - Fc); i += 256) {
            int o = og * 64 + i / (FP - Fc), cc = Fc + i % (FP - Fc);
            g_W2Th[((size_t)b * Dc + o) * FP + cc] = __float2half_rn(0.0f);
        }
    }
}

// ============================================================================
// Kernel E: out[b] = QCh[b] @ W2Th[b]^T + fcb.  grid (4, 64, 4), 256 thr.
// ============================================================================
__global__ void __launch_bounds__(256, 2)
out_gemm(const float* __restrict__ fcb, float* __restrict__ out)
{
    extern __shared__ __align__(16) char smraw[];
    __half* smh = (__half*)smraw;
    const uint32_t sbase = smem_u32(smraw);
    const int b = blockIdx.z;
    const __half* A  = g_QCh + (size_t)b * Lc * FP;
    const __half* Bw = g_W2Th + (size_t)b * Dc * FP;
    float* C = out + (size_t)b * Lc * Dc;

    const int m0 = blockIdx.y * 128;
    const int n0 = blockIdx.x * 128;

    float acc[4][4][4] = {};
    gemm_mainloop(A, Bw, FP, FP / 32, m0, n0, smh, sbase, acc);

    const int tid = threadIdx.x;
    const int wid = tid >> 5;
    const int lane = tid & 31;
    const int g = lane >> 2;
    const int t = lane & 3;
    const int mw = (wid >> 2) * 64;
    const int nw = (wid & 3) * 32;

#pragma unroll
    for (int i = 0; i < 4; i++) {
        const int row0 = m0 + mw + 16 * i + g;
#pragma unroll
        for (int j = 0; j < 4; j++) {
            const int col = n0 + nw + 8 * j + 2 * t;
            float2 bv = *(const float2*)(fcb + col);
            float2 o0, o1;
            o0.x = acc[i][j][0] + bv.x;  o0.y = acc[i][j][1] + bv.y;
            o1.x = acc[i][j][2] + bv.x;  o1.y = acc[i][j][3] + bv.y;
            *(float2*)(C + (size_t)row0 * Dc + col) = o0;
            *(float2*)(C + (size_t)(row0 + 8) * Dc + col) = o1;
        }
    }
}

// ============================================================================
// launch
// ============================================================================
extern "C" void kernel_launch(void* const* d_in, const int* in_sizes, int n_in,
                              void* d_out, int out_size)
{
    const float* query = (const float*)d_in[0];
    const float* key   = (const float*)d_in[1];
    const float* value = (const float*)d_in[2];
    const float* pos   = (const float*)d_in[3];
    const float* Wq    = (const float*)d_in[4];
    const float* bq    = (const float*)d_in[5];
    const float* Wk    = (const float*)d_in[6];
    const float* bk    = (const float*)d_in[7];
    const float* Wv    = (const float*)d_in[8];
    const float* bv    = (const float*)d_in[9];
    const float* gK    = (const float*)d_in[10];
    const float* betaK = (const float*)d_in[11];
    const float* gV    = (const float*)d_in[12];
    const float* betaV = (const float*)d_in[13];
    const float* fcW   = (const float*)d_in[14];
    const float* fcb   = (const float*)d_in[15];

    float* att_out  = (float*)d_out;
    float* attn_out = att_out + ATT_ELEMS;

    cudaFuncSetAttribute(proj_fused, cudaFuncAttributeMaxDynamicSharedMemorySize, SMEM_PROJ);
    cudaFuncSetAttribute(out_gemm,  cudaFuncAttributeMaxDynamicSharedMemorySize, SMEM_MAIN);
    cudaFuncSetAttribute(attn_mma,  cudaFuncAttributeMaxDynamicSharedMemorySize, SMEM_ATTN);

    // 0) convert inputs + weights to fp16
    xcvt<<<dim3((unsigned)(BLD / 4 / 256), 3), 256>>>(query, key, value);
    wcvt<<<dim3(Dc * Dc / 4 / 256, 3), 256>>>(Wq, Wk, Wv);
    // 1) fused projections + LN + concat (fp16 MMA, fp32 accum)
    proj_fused<<<dim3(4, 256, 3), 256, SMEM_PROJ>>>(bq, bk, bv,
                                                     gK, betaK, gV, betaV, pos);
    // 2) attn partials via fp16 MMA (deterministic)
    attn_mma<<<dim3(NSPLIT, Hc, Bc), 256, SMEM_ATTN>>>();
    // 3) reduce + scale -> attn output
    attn_reduce<<<(unsigned)((ATTN_ELEMS + 255) / 256), 256>>>(attn_out);
    // 4) fold attn into fc weights (fp16 out)
    w2t_kernel<<<dim3(8, Bc * Hc), 256>>>(attn_out, fcW);
    // 5) output GEMM (fp16 MMA), batched over z
    out_gemm<<<dim3(4, 64, Bc), 256, SMEM_MAIN>>>(fcb, att_out);
}

// round 12
// speedup vs baseline: 1.8495x; 1.0727x over previous
#include <cuda_runtime.h>
#include <cuda_fp16.h>
#include <cstdint>

// ---------------- problem constants ----------------
#define Bc 4
#define Lc 8192
#define Dc 512
#define Hc 8
#define DKc 64
#define Ec 65           // DK + PD
#define Fc 520          // H * E
#define FP 544          // padded F (multiple of 32)
#define EHH 72          // padded per-head width (halfs, 144B = 9x16B)
#define NSPLIT 16
#define LCHUNK (Lc / NSPLIT)   // 512

#define ATT_ELEMS  ((size_t)Bc * Lc * Dc)
#define ATTN_ELEMS ((size_t)Bc * Hc * Ec * Ec)
#define BLD ((size_t)Bc * Lc * Dc)

// ---------------- scratch (device globals; no allocs allowed) ----------------
__device__ __half g_Xh[3][BLD];                      // fp16 query/key/value
__device__ __half g_Wh[3][(size_t)Dc * Dc];          // fp16 Wq/Wk/Wv
__device__ __half g_QCh[(size_t)Bc * Lc * FP];       // concat q, fp16, pad zeroed
__device__ __half g_KHh[(size_t)Bc * Hc * Lc * EHH]; // LN'd k, fp16 (rounded once)
__device__ __half g_VHh[(size_t)Bc * Hc * Lc * EHH]; // LN'd v, fp16
__device__ float  g_part[(size_t)Bc * Hc * NSPLIT * Ec * Ec];
__device__ __half g_W2Th[(size_t)Bc * Dc * FP];      // folded fc weights, fp16

// ============================================================================
// helpers
// ============================================================================
__device__ __forceinline__ uint32_t smem_u32(const void* p) {
    uint32_t a;
    asm("{ .reg .u64 t; cvta.to.shared.u64 t, %1; cvt.u32.u64 %0, t; }" : "=r"(a) : "l"(p));
    return a;
}
__device__ __forceinline__ void cp16(uint32_t dst, const void* src) {
    asm volatile("cp.async.ca.shared.global [%0], [%1], 16;" :: "r"(dst), "l"(src));
}
#define CP_COMMIT() asm volatile("cp.async.commit_group;" ::: "memory")
#define CP_WAIT0()  asm volatile("cp.async.wait_group 0;" ::: "memory")
#define CP_WAIT1()  asm volatile("cp.async.wait_group 1;" ::: "memory")

__device__ __forceinline__ void mma_f16(float c[4], const uint32_t a[4], const uint32_t b[2]) {
    asm volatile(
        "mma.sync.aligned.m16n8k16.row.col.f32.f16.f16.f32 "
        "{%0,%1,%2,%3}, {%4,%5,%6,%7}, {%8,%9}, {%0,%1,%2,%3};"
        : "+f"(c[0]), "+f"(c[1]), "+f"(c[2]), "+f"(c[3])
        : "r"(a[0]), "r"(a[1]), "r"(a[2]), "r"(a[3]), "r"(b[0]), "r"(b[1]));
}
#define LDSM_X4(r0, r1, r2, r3, addr) \
    asm volatile("ldmatrix.sync.aligned.m8n8.x4.shared.b16 {%0,%1,%2,%3}, [%4];" \
        : "=r"(r0), "=r"(r1), "=r"(r2), "=r"(r3) : "r"(addr))

// ============================================================================
// fp16 GEMM mainloop: C[M,N] = A[M,K] @ B[N,K]^T, fp32 accum.
// 128x128 CTA tile, 256 thr (8 warps, warp tile 64x32), K-block 32,
// cp.async 3-stage, fragments via ldmatrix.x4.
// ============================================================================
#define SSTRH 40                        // smem row stride in halfs (80B)
#define ATILEH (128 * SSTRH)            // 5120 halfs per operand per stage
#define STAGEH (2 * ATILEH)             // 10240 halfs per stage
#define NSTAGE 3
#define SMEM_MAIN (NSTAGE * STAGEH * 2) // 61440 bytes
#define SMEM_PROJ (128 * 132 * 4)       // 67584 bytes (epilogue staging)

__device__ __forceinline__ void gemm_copy_stage(
    const __half* __restrict__ A, const __half* __restrict__ Bw,
    int lda, int m0, int n0, int kb, uint32_t sbase, int r0, int c)
{
    const int s = kb % NSTAGE;
    const int k0 = kb << 5;
    uint32_t as = sbase + (uint32_t)(s * STAGEH) * 2u;
    uint32_t bs = as + (uint32_t)ATILEH * 2u;
#pragma unroll
    for (int rr = 0; rr < 2; rr++) {
        const int row = r0 + rr * 64;
        uint32_t doff = (uint32_t)(row * SSTRH + c * 8) * 2u;
        cp16(as + doff, A + (size_t)(m0 + row) * lda + k0 + c * 8);
        cp16(bs + doff, Bw + (size_t)(n0 + row) * lda + k0 + c * 8);
    }
}

__device__ __forceinline__ void gemm_mainloop(
    const __half* __restrict__ A, const __half* __restrict__ Bw,
    int lda, int NKB, int m0, int n0,
    uint32_t sbase, float acc[4][4][4])
{
    const int tid = threadIdx.x;
    const int wid = tid >> 5;
    const int lane = tid & 31;
    const int mw = (wid >> 2) * 64;
    const int nw = (wid & 3) * 32;
    const int r0 = tid >> 2;              // copy row 0..63 (+64)
    const int cc = tid & 3;               // copy chunk

    // ldmatrix per-thread address offsets (halfs)
    const int rA = (lane & 7) + (lane & 8);       // row within 16-block
    const int cA = (lane & 16) >> 1;              // 0 or 8 (k offset)
    const int rB = (lane & 7) + ((lane & 16) >> 1);
    const int cB = (lane & 8);                    // 0 or 8
    const uint32_t aoff = (uint32_t)((mw + rA) * SSTRH + cA) * 2u;
    const uint32_t boff = (uint32_t)((nw + rB) * SSTRH + cB) * 2u;

    gemm_copy_stage(A, Bw, lda, m0, n0, 0, sbase, r0, cc);
    CP_COMMIT();
    gemm_copy_stage(A, Bw, lda, m0, n0, 1, sbase, r0, cc);
    CP_COMMIT();

#pragma unroll 1
    for (int kb = 0; kb < NKB; kb++) {
        if (kb + 1 < NKB) { CP_WAIT1(); } else { CP_WAIT0(); }
        __syncthreads();
        if (kb + 2 < NKB) {
            gemm_copy_stage(A, Bw, lda, m0, n0, kb + 2, sbase, r0, cc);
            CP_COMMIT();
        }

        const uint32_t abase = sbase + (uint32_t)((kb % NSTAGE) * STAGEH) * 2u;
        const uint32_t bbase = abase + (uint32_t)ATILEH * 2u;
#pragma unroll
        for (int kk = 0; kk < 32; kk += 16) {
            uint32_t af[4][4];
#pragma unroll
            for (int i = 0; i < 4; i++)
                LDSM_X4(af[i][0], af[i][1], af[i][2], af[i][3],
                        abase + aoff + (uint32_t)((16 * i) * SSTRH + kk) * 2u);
            uint32_t bf[4][2];
#pragma unroll
            for (int jj = 0; jj < 2; jj++)
                LDSM_X4(bf[2 * jj][0], bf[2 * jj][1], bf[2 * jj + 1][0], bf[2 * jj + 1][1],
                        bbase + boff + (uint32_t)((16 * jj) * SSTRH + kk) * 2u);
#pragma unroll
            for (int i = 0; i < 4; i++)
#pragma unroll
                for (int j = 0; j < 4; j++)
                    mma_f16(acc[i][j], af[i], bf[j]);
        }
    }
}

// ============================================================================
// Kernel X: convert inputs/weights to fp16 (vectorized)
// ============================================================================
__global__ void xcvt(const float* __restrict__ Xq, const float* __restrict__ Xk,
                     const float* __restrict__ Xv)
{
    const int op = blockIdx.y;
    const float* X = (op == 0) ? Xq : (op == 1) ? Xk : Xv;
    const size_t i4 = (size_t)blockIdx.x * 256 + threadIdx.x;
    float4 v = ((const float4*)X)[i4];
    __half2* dst = (__half2*)(g_Xh[op] + i4 * 4);
    dst[0] = __floats2half2_rn(v.x, v.y);
    dst[1] = __floats2half2_rn(v.z, v.w);
}

__global__ void wcvt(const float* __restrict__ Wq, const float* __restrict__ Wk,
                     const float* __restrict__ Wv)
{
    const int op = blockIdx.y;
    const float* W = (op == 0) ? Wq : (op == 1) ? Wk : Wv;
    const size_t i4 = (size_t)blockIdx.x * 256 + threadIdx.x;
    float4 v = ((const float4*)W)[i4];
    __half2* dst = (__half2*)(g_Wh[op] + i4 * 4);
    dst[0] = __floats2half2_rn(v.x, v.y);
    dst[1] = __floats2half2_rn(v.z, v.w);
}

// ============================================================================
// Kernel A: fused projection + LN + concat.  grid (4, 256, 3), 256 thr.
// ============================================================================
#define CSTR 132

__global__ void __launch_bounds__(256, 2)
proj_fused(const float* __restrict__ bq, const float* __restrict__ bk,
           const float* __restrict__ bv,
           const float* __restrict__ gK, const float* __restrict__ betaK,
           const float* __restrict__ gV, const float* __restrict__ betaV,
           const float* __restrict__ pos)
{
    extern __shared__ __align__(16) char smraw[];
    float* smf = (float*)smraw;
    const uint32_t sbase = smem_u32(smraw);
    const int mode = blockIdx.z;
    const __half* A = g_Xh[mode];
    const __half* W = g_Wh[mode];
    const float* bias = (mode == 0) ? bq : (mode == 1) ? bk : bv;
    const float* gamm = (mode == 1) ? gK : gV;
    const float* beta = (mode == 1) ? betaK : betaV;

    const int m0 = blockIdx.y * 128;
    const int n0 = blockIdx.x * 128;

    float acc[4][4][4] = {};
    gemm_mainloop(A, W, Dc, Dc / 32, m0, n0, sbase, acc);

    // ---- stage tile (+bias) into smem as fp32 ----
    __syncthreads();
    const int tid = threadIdx.x;
    const int wid = tid >> 5;
    const int lane = tid & 31;
    const int g = lane >> 2;
    const int t = lane & 3;
    const int mw = (wid >> 2) * 64;
    const int nw = (wid & 3) * 32;

#pragma unroll
    for (int i = 0; i < 4; i++) {
        const int r0 = mw + 16 * i + g;
#pragma unroll
        for (int j = 0; j < 4; j++) {
            const int col = nw + 8 * j + 2 * t;
            float2 bv2 = *(const float2*)(bias + n0 + col);
            smf[r0 * CSTR + col]       = acc[i][j][0] + bv2.x;
            smf[r0 * CSTR + col + 1]   = acc[i][j][1] + bv2.y;
            smf[(r0 + 8) * CSTR + col]     = acc[i][j][2] + bv2.x;
            smf[(r0 + 8) * CSTR + col + 1] = acc[i][j][3] + bv2.y;
        }
    }
    __syncthreads();

    // ---- per-row epilogue: 8 warps x 16 rows ----
    for (int rr = 0; rr < 16; rr++) {
        const int r = wid * 16 + rr;
        const int m = m0 + r;                 // = b*L + l
        const int b = m >> 13, l = m & (Lc - 1);
        const float pv = pos[m];
#pragma unroll
        for (int hh = 0; hh < 2; hh++) {
            const int h = (n0 >> 6) + hh;
            float x0 = smf[r * CSTR + 64 * hh + lane];
            float x1 = smf[r * CSTR + 64 * hh + lane + 32];
            if (mode == 0) {
                __half* qrow = &g_QCh[(size_t)m * FP + h * Ec];
                if (lane == 0) qrow[0] = __float2half_rn(pv);
                qrow[1 + lane] = __float2half_rn(x0);
                qrow[1 + lane + 32] = __float2half_rn(x1);
                if (hh == 1 && n0 == 384 && lane < (FP - Fc))
                    g_QCh[(size_t)m * FP + Fc + lane] = __float2half_rn(0.0f);
            } else {
                float s = x0 + x1, sq = x0 * x0 + x1 * x1;
#pragma unroll
                for (int off = 16; off; off >>= 1) {
                    s  += __shfl_xor_sync(0xffffffffu, s,  off);
                    sq += __shfl_xor_sync(0xffffffffu, sq, off);
                }
                float mean = s * (1.0f / 64.0f);
                float var = sq * (1.0f / 64.0f) - mean * mean;
                float rstd = rsqrtf(var + 1e-5f);
                float y0 = (x0 - mean) * rstd * gamm[h * DKc + lane] + beta[h * DKc + lane];
                float y1 = (x1 - mean) * rstd * gamm[h * DKc + lane + 32] + beta[h * DKc + lane + 32];
                __half* orow = ((mode == 1) ? g_KHh : g_VHh) +
                               (((size_t)b * Hc + h) * Lc + l) * EHH;
                if (lane == 0) orow[0] = __float2half_rn(pv);
                orow[1 + lane] = __float2half_rn(y0);
                orow[1 + lane + 32] = __float2half_rn(y1);
                if (lane < (EHH - Ec)) orow[Ec + lane] = __float2half_rn(0.0f); // pad 65..71
            }
        }
    }
}

// ============================================================================
// Kernel B: attn partials via fp16 MMA.  K/V tiles staged as fp16 [l][72].
// Fragments built via transposed smem reads (half loads + pack; conflict-free:
// 16 distinct words per fragment access, 2 lanes share a word -> broadcast).
// fp32 accum, fixed order -> deterministic.
// ============================================================================
#define AST 72                          // smem row stride (halfs)
#define ATILE_H (32 * AST)              // 2304 halfs per operand per stage
#define ASTG (2 * ATILE_H)              // 4608 halfs per stage
#define ANST 3
#define SMEM_ATTN ((ANST * ASTG + 128) * 2)   // 27904 bytes

__global__ void __launch_bounds__(256, 2)
attn_mma()
{
    extern __shared__ __align__(16) __half smha[];
    const uint32_t sbase = smem_u32(smha);
    const int split = blockIdx.x, h = blockIdx.y, b = blockIdx.z;
    const int tid = threadIdx.x;
    const int wid = tid >> 5, lane = tid & 31;
    const int g = lane >> 2, t = lane & 3;
    const int mw = (wid >> 2) * 48;       // 2 warp-rows of 48
    const int nw = (wid & 3) * 24;        // 4 warp-cols of 24
    const int NKB = LCHUNK / 32;          // 16

    const __half* Kb = g_KHh + (((size_t)b * Hc + h) * Lc + (size_t)split * LCHUNK) * EHH;
    const __half* Vb = g_VHh + (((size_t)b * Hc + h) * Lc + (size_t)split * LCHUNK) * EHH;

    auto issue = [&](int kb) {
        const int s = kb % ANST;
        const int l0 = kb << 5;
        uint32_t base = sbase + (uint32_t)(s * ASTG) * 2u;
#pragma unroll
        for (int c = 0; c < 3; c++) {
            int idx = tid + (c << 8);
            if (idx < 576) {                       // 32 rows x 9 chunks x 2 ops
                int op = idx >= 288;
                int i2 = op ? idx - 288 : idx;
                int row = i2 / 9, ch = i2 % 9;
                const __half* src = (op ? Vb : Kb) + (size_t)(l0 + row) * EHH + ch * 8;
                cp16(base + (uint32_t)(op * ATILE_H + row * AST + ch * 8) * 2u, src);
            }
        }
        CP_COMMIT();
    };

    issue(0);
    issue(1);

    // validity predicates (cols 65..71 stored zeros; >=72 OOB of row)
    bool mok0[3], mok1[3], nok[3];
#pragma unroll
    for (int i = 0; i < 3; i++) {
        int d = mw + 16 * i + g;
        mok0[i] = (d < EHH);
        mok1[i] = (d + 8 < EHH);
    }
#pragma unroll
    for (int j = 0; j < 3; j++) nok[j] = (nw + 8 * j + g < EHH);

    float acc[3][3][4] = {};

#pragma unroll 1
    for (int kb = 0; kb < NKB; kb++) {
        if (kb + 1 < NKB) { CP_WAIT1(); } else { CP_WAIT0(); }
        __syncthreads();
        if (kb + 2 < NKB) issue(kb + 2);

        const __half* ks = smha + (kb % ANST) * ASTG;
        const __half* vs = ks + ATILE_H;
#pragma unroll
        for (int kk = 0; kk < 32; kk += 16) {
            const __half* k0p = ks + (kk + 2 * t) * AST;     // l = kk+2t
            const __half* v0p = vs + (kk + 2 * t) * AST;
            uint32_t af[3][4];
#pragma unroll
            for (int i = 0; i < 3; i++) {
                int d = mw + 16 * i + g;
                __half2 p;
                if (mok0[i]) { p = __halves2half2(k0p[d], k0p[AST + d]); af[i][0] = *(uint32_t*)&p; } else af[i][0] = 0u;
                if (mok1[i]) { p = __halves2half2(k0p[d + 8], k0p[AST + d + 8]); af[i][1] = *(uint32_t*)&p; } else af[i][1] = 0u;
                if (mok0[i]) { p = __halves2half2(k0p[8 * AST + d], k0p[9 * AST + d]); af[i][2] = *(uint32_t*)&p; } else af[i][2] = 0u;
                if (mok1[i]) { p = __halves2half2(k0p[8 * AST + d + 8], k0p[9 * AST + d + 8]); af[i][3] = *(uint32_t*)&p; } else af[i][3] = 0u;
            }
            uint32_t bf[3][2];
#pragma unroll
            for (int j = 0; j < 3; j++) {
                int e = nw + 8 * j + g;
                if (nok[j]) {
                    __half2 p0 = __halves2half2(v0p[e], v0p[AST + e]);
                    __half2 p1 = __halves2half2(v0p[8 * AST + e], v0p[9 * AST + e]);
                    bf[j][0] = *(uint32_t*)&p0;
                    bf[j][1] = *(uint32_t*)&p1;
                } else { bf[j][0] = 0u; bf[j][1] = 0u; }
            }
#pragma unroll
            for (int i = 0; i < 3; i++)
#pragma unroll
                for (int j = 0; j < 3; j++)
                    mma_f16(acc[i][j], af[i], bf[j]);
        }
    }

    // store partials (valid region 65x65 only)
    float* out = &g_part[(((size_t)b * Hc + h) * NSPLIT + split) * Ec * Ec];
#pragma unroll
    for (int i = 0; i < 3; i++) {
        const int m = mw + 16 * i + g;
#pragma unroll
        for (int j = 0; j < 3; j++) {
            const int n = nw + 8 * j + 2 * t;
            if (m < Ec) {
                if (n < Ec)     out[m * Ec + n]     = acc[i][j][0];
                if (n + 1 < Ec) out[m * Ec + n + 1] = acc[i][j][1];
            }
            if (m + 8 < Ec) {
                if (n < Ec)     out[(m + 8) * Ec + n]     = acc[i][j][2];
                if (n + 1 < Ec) out[(m + 8) * Ec + n + 1] = acc[i][j][3];
            }
        }
    }
}

// ============================================================================
// Kernel C: reduce partials, scale by 1/L
// ============================================================================
__global__ void attn_reduce(float* __restrict__ attn_out)
{
    const size_t idx = (size_t)blockIdx.x * blockDim.x + threadIdx.x;
    if (idx >= ATTN_ELEMS) return;
    const size_t bh = idx / (Ec * Ec);
    const size_t de = idx % (Ec * Ec);
    float s = 0.0f;
#pragma unroll
    for (int sp = 0; sp < NSPLIT; sp++)
        s += g_part[(bh * NSPLIT + sp) * (Ec * Ec) + de];
    attn_out[idx] = s * (1.0f / (float)Lc);
}

// ============================================================================
// Kernel D: W2Th[b,o,h*65+d] = sum_e attn[b,h,d,e]*fcW[o,h*65+e]   (fp16 out)
// ============================================================================
__global__ void __launch_bounds__(256)
w2t_kernel(const float* __restrict__ attn, const float* __restrict__ fcW)
{
    const int og = blockIdx.x;          // 0..7 (64 o's each)
    const int bh = blockIdx.y;          // 0..31
    const int b = bh >> 3, h = bh & 7;
    __shared__ float sa[Ec * 68];       // sa[e*68 + d] = attn[d][e]  (transposed)
    __shared__ float sw[64 * 66];       // sw[o*66 + e] = fcW row
    const int tid = threadIdx.x;

    for (int i = tid; i < Ec * Ec; i += 256) {
        int d = i / Ec, e = i % Ec;
        sa[e * 68 + d] = attn[((size_t)bh * Ec + d) * Ec + e];
    }
    for (int i = tid; i < 64 * Ec; i += 256) {
        int o = i / Ec, e = i % Ec;
        sw[o * 66 + e] = fcW[(size_t)(og * 64 + o) * Fc + h * Ec + e];
    }
    __syncthreads();

    for (int idx = tid; idx < 64 * Ec; idx += 256) {
        int o = idx / Ec, d = idx % Ec;
        const float* wr = &sw[o * 66];
        float s = 0.0f;
#pragma unroll
        for (int e = 0; e < Ec; e++) s += wr[e] * sa[e * 68 + d];
        g_W2Th[((size_t)b * Dc + og * 64 + o) * FP + h * Ec + d] = __float2half_rn(s);
    }
    if (h == 0) {
        for (int i = tid; i < 64 * (FP - Fc); i += 256) {
            int o = og * 64 + i / (FP - Fc), cc = Fc + i % (FP - Fc);
            g_W2Th[((size_t)b * Dc + o) * FP + cc] = __float2half_rn(0.0f);
        }
    }
}

// ============================================================================
// Kernel E: out[b] = QCh[b] @ W2Th[b]^T + fcb.  grid (4, 64, 4), 256 thr.
// ============================================================================
__global__ void __launch_bounds__(256, 2)
out_gemm(const float* __restrict__ fcb, float* __restrict__ out)
{
    extern __shared__ __align__(16) char smraw[];
    const uint32_t sbase = smem_u32(smraw);
    const int b = blockIdx.z;
    const __half* A  = g_QCh + (size_t)b * Lc * FP;
    const __half* Bw = g_W2Th + (size_t)b * Dc * FP;
    float* C = out + (size_t)b * Lc * Dc;

    const int m0 = blockIdx.y * 128;
    const int n0 = blockIdx.x * 128;

    float acc[4][4][4] = {};
    gemm_mainloop(A, Bw, FP, FP / 32, m0, n0, sbase, acc);

    const int tid = threadIdx.x;
    const int wid = tid >> 5;
    const int lane = tid & 31;
    const int g = lane >> 2;
    const int t = lane & 3;
    const int mw = (wid >> 2) * 64;
    const int nw = (wid & 3) * 32;

#pragma unroll
    for (int i = 0; i < 4; i++) {
        const int row0 = m0 + mw + 16 * i + g;
#pragma unroll
        for (int j = 0; j < 4; j++) {
            const int col = n0 + nw + 8 * j + 2 * t;
            float2 bv = *(const float2*)(fcb + col);
            float2 o0, o1;
            o0.x = acc[i][j][0] + bv.x;  o0.y = acc[i][j][1] + bv.y;
            o1.x = acc[i][j][2] + bv.x;  o1.y = acc[i][j][3] + bv.y;
            *(float2*)(C + (size_t)row0 * Dc + col) = o0;
            *(float2*)(C + (size_t)(row0 + 8) * Dc + col) = o1;
        }
    }
}

// ============================================================================
// launch
// ============================================================================
extern "C" void kernel_launch(void* const* d_in, const int* in_sizes, int n_in,
                              void* d_out, int out_size)
{
    const float* query = (const float*)d_in[0];
    const float* key   = (const float*)d_in[1];
    const float* value = (const float*)d_in[2];
    const float* pos   = (const float*)d_in[3];
    const float* Wq    = (const float*)d_in[4];
    const float* bq    = (const float*)d_in[5];
    const float* Wk    = (const float*)d_in[6];
    const float* bk    = (const float*)d_in[7];
    const float* Wv    = (const float*)d_in[8];
    const float* bv    = (const float*)d_in[9];
    const float* gK    = (const float*)d_in[10];
    const float* betaK = (const float*)d_in[11];
    const float* gV    = (const float*)d_in[12];
    const float* betaV = (const float*)d_in[13];
    const float* fcW   = (const float*)d_in[14];
    const float* fcb   = (const float*)d_in[15];

    float* att_out  = (float*)d_out;
    float* attn_out = att_out + ATT_ELEMS;

    cudaFuncSetAttribute(proj_fused, cudaFuncAttributeMaxDynamicSharedMemorySize, SMEM_PROJ);
    cudaFuncSetAttribute(out_gemm,  cudaFuncAttributeMaxDynamicSharedMemorySize, SMEM_MAIN);
    cudaFuncSetAttribute(attn_mma,  cudaFuncAttributeMaxDynamicSharedMemorySize, SMEM_ATTN);

    // 0) convert inputs + weights to fp16
    xcvt<<<dim3((unsigned)(BLD / 4 / 256), 3), 256>>>(query, key, value);
    wcvt<<<dim3(Dc * Dc / 4 / 256, 3), 256>>>(Wq, Wk, Wv);
    // 1) fused projections + LN + concat (fp16 MMA, fp32 accum)
    proj_fused<<<dim3(4, 256, 3), 256, SMEM_PROJ>>>(bq, bk, bv,
                                                     gK, betaK, gV, betaV, pos);
    // 2) attn partials via fp16 MMA (deterministic)
    attn_mma<<<dim3(NSPLIT, Hc, Bc), 256, SMEM_ATTN>>>();
    // 3) reduce + scale -> attn output
    attn_reduce<<<(unsigned)((ATTN_ELEMS + 255) / 256), 256>>>(attn_out);
    // 4) fold attn into fc weights (fp16 out)
    w2t_kernel<<<dim3(8, Bc * Hc), 256>>>(attn_out, fcW);
    // 5) output GEMM (fp16 MMA), batched over z
    out_gemm<<<dim3(4, 64, Bc), 256, SMEM_MAIN>>>(fcb, att_out);
}